// round 3
// baseline (speedup 1.0000x reference)
#include <cuda_runtime.h>
#include <math.h>

#define B_   64
#define C_   1000
#define F_   2048
#define KS   16     // split-K for mega / mem
#define KSC  32     // split-K for cos gemm
#define CP   1024   // padded C stride

// ---------------- scratch (static __device__, no allocations) ----------------
__device__ float g_p_dot[KS][B_ * CP];
__device__ float g_p_hall[KS][B_ * CP];
__device__ float g_p_sel[KS][B_ * F_];
__device__ float g_p_mem[KS][B_ * F_];
__device__ float g_p_cos[KSC][B_ * CP];
__device__ float g_hall[B_ * CP];
__device__ float g_vm[B_ * CP];
__device__ float g_feat[B_ * F_];
__device__ float g_cn2[CP];
__device__ float g_wn[CP];
__device__ float g_xn2[B_];
__device__ float g_reach[B_];
__device__ float g_scale[B_];

// ---------------- f32x2 helpers ----------------
__device__ __forceinline__ unsigned long long pack2(float v) {
    unsigned long long r;
    asm("mov.b64 %0, {%1, %1};" : "=l"(r) : "f"(v));
    return r;
}
__device__ __forceinline__ void fma2(unsigned long long& d, unsigned long long a, unsigned long long b) {
    asm("fma.rn.f32x2 %0, %1, %2, %0;" : "+l"(d) : "l"(a), "l"(b));
}

// ---------------- row-wise squared norms / norms ----------------
__global__ __launch_bounds__(256) void norms_kernel(const float* __restrict__ centroids,
                                                    const float* __restrict__ W_cos,
                                                    const float* __restrict__ x) {
    int bid = blockIdx.x;
    const float* src;
    int mode, idx;
    if (bid < C_)            { src = centroids + (size_t)bid * F_;        mode = 0; idx = bid; }
    else if (bid < 2 * C_)   { src = W_cos + (size_t)(bid - C_) * F_;     mode = 1; idx = bid - C_; }
    else                     { src = x + (size_t)(bid - 2 * C_) * F_;     mode = 2; idx = bid - 2 * C_; }
    const float4* s4 = (const float4*)src;
    float s = 0.f;
    for (int i = threadIdx.x; i < F_ / 4; i += 256) {
        float4 v = s4[i];
        s += v.x * v.x + v.y * v.y + v.z * v.z + v.w * v.w;
    }
#pragma unroll
    for (int o = 16; o > 0; o >>= 1) s += __shfl_xor_sync(0xffffffffu, s, o);
    __shared__ float red[8];
    if ((threadIdx.x & 31) == 0) red[threadIdx.x >> 5] = s;
    __syncthreads();
    if (threadIdx.x == 0) {
        float tot = 0.f;
#pragma unroll
        for (int w = 0; w < 8; w++) tot += red[w];
        if (mode == 0)      g_cn2[idx] = tot;
        else if (mode == 1) g_wn[idx]  = sqrtf(tot);
        else                g_xn2[idx] = tot;
    }
}

// ---------------- compute micro-kernel: 4x8 via 16 FFMA2, from smem tile ----------------
// As/Bs layout: [16][68] floats.
__device__ __forceinline__ void tile_mma(const float (*As)[68], const float (*Bs)[68],
                                         int ty, int tx, unsigned long long acc[4][4]) {
#pragma unroll
    for (int kk = 0; kk < 16; kk++) {
        float4 av = *(const float4*)&As[kk][ty * 4];
        ulonglong2 bp = *(const ulonglong2*)&Bs[kk][tx * 8];
        ulonglong2 bq = *(const ulonglong2*)&Bs[kk][tx * 8 + 4];
        unsigned long long a0 = pack2(av.x), a1 = pack2(av.y), a2 = pack2(av.z), a3 = pack2(av.w);
        fma2(acc[0][0], a0, bp.x); fma2(acc[0][1], a0, bp.y); fma2(acc[0][2], a0, bq.x); fma2(acc[0][3], a0, bq.y);
        fma2(acc[1][0], a1, bp.x); fma2(acc[1][1], a1, bp.y); fma2(acc[1][2], a1, bq.x); fma2(acc[1][3], a1, bq.y);
        fma2(acc[2][0], a2, bp.x); fma2(acc[2][1], a2, bp.y); fma2(acc[2][2], a2, bq.x); fma2(acc[2][3], a2, bq.y);
        fma2(acc[3][0], a3, bp.x); fma2(acc[3][1], a3, bp.y); fma2(acc[3][2], a3, bq.x); fma2(acc[3][3], a3, bq.y);
    }
}

// ---------------- NT GEMM core: 64x64 tile, BK=16, 128 thr, double-buffered ----------------
// P[m, n0+n] = sum_{k in [k0,k0+klen)} A[m,k] * Bm[n0+n, k]; klen % 16 == 0.
__device__ __forceinline__ void gemm64_nt(const float* __restrict__ A, int lda,
                                          const float* __restrict__ Bm, int ldb,
                                          float* __restrict__ P, int ldp,
                                          int N, int n0, int k0, int klen) {
    __shared__ float As[2][16][68];
    __shared__ float Bs[2][16][68];
    const int tid = threadIdx.x;
    const int tx  = tid & 7;
    const int ty  = tid >> 3;
    const int lr  = tid >> 2;
    const int lkq = (tid & 3) * 4;
    const int br0 = n0 + lr, br1 = n0 + lr + 32;
    const bool v0 = br0 < N, v1 = br1 < N;

    unsigned long long acc[4][4];
#pragma unroll
    for (int i = 0; i < 4; i++)
#pragma unroll
        for (int j = 0; j < 4; j++) acc[i][j] = 0ull;

    // first tile
    {
        float4 a0 = *(const float4*)&A[(size_t)lr * lda + k0 + lkq];
        float4 a1 = *(const float4*)&A[(size_t)(lr + 32) * lda + k0 + lkq];
        float4 b0 = v0 ? *(const float4*)&Bm[(size_t)br0 * ldb + k0 + lkq] : make_float4(0.f,0.f,0.f,0.f);
        float4 b1 = v1 ? *(const float4*)&Bm[(size_t)br1 * ldb + k0 + lkq] : make_float4(0.f,0.f,0.f,0.f);
        As[0][lkq+0][lr] = a0.x; As[0][lkq+1][lr] = a0.y; As[0][lkq+2][lr] = a0.z; As[0][lkq+3][lr] = a0.w;
        As[0][lkq+0][lr+32] = a1.x; As[0][lkq+1][lr+32] = a1.y; As[0][lkq+2][lr+32] = a1.z; As[0][lkq+3][lr+32] = a1.w;
        Bs[0][lkq+0][lr] = b0.x; Bs[0][lkq+1][lr] = b0.y; Bs[0][lkq+2][lr] = b0.z; Bs[0][lkq+3][lr] = b0.w;
        Bs[0][lkq+0][lr+32] = b1.x; Bs[0][lkq+1][lr+32] = b1.y; Bs[0][lkq+2][lr+32] = b1.z; Bs[0][lkq+3][lr+32] = b1.w;
    }
    __syncthreads();

    int buf = 0;
    for (int kb = k0; kb < k0 + klen; kb += 16) {
        const bool hn = (kb + 16) < k0 + klen;
        float4 na0, na1, nb0, nb1;
        if (hn) {
            int kn = kb + 16;
            na0 = *(const float4*)&A[(size_t)lr * lda + kn + lkq];
            na1 = *(const float4*)&A[(size_t)(lr + 32) * lda + kn + lkq];
            nb0 = v0 ? *(const float4*)&Bm[(size_t)br0 * ldb + kn + lkq] : make_float4(0.f,0.f,0.f,0.f);
            nb1 = v1 ? *(const float4*)&Bm[(size_t)br1 * ldb + kn + lkq] : make_float4(0.f,0.f,0.f,0.f);
        }
        tile_mma(As[buf], Bs[buf], ty, tx, acc);
        if (hn) {
            int nb = buf ^ 1;
            As[nb][lkq+0][lr] = na0.x; As[nb][lkq+1][lr] = na0.y; As[nb][lkq+2][lr] = na0.z; As[nb][lkq+3][lr] = na0.w;
            As[nb][lkq+0][lr+32] = na1.x; As[nb][lkq+1][lr+32] = na1.y; As[nb][lkq+2][lr+32] = na1.z; As[nb][lkq+3][lr+32] = na1.w;
            Bs[nb][lkq+0][lr] = nb0.x; Bs[nb][lkq+1][lr] = nb0.y; Bs[nb][lkq+2][lr] = nb0.z; Bs[nb][lkq+3][lr] = nb0.w;
            Bs[nb][lkq+0][lr+32] = nb1.x; Bs[nb][lkq+1][lr+32] = nb1.y; Bs[nb][lkq+2][lr+32] = nb1.z; Bs[nb][lkq+3][lr+32] = nb1.w;
        }
        __syncthreads();
        buf ^= 1;
    }

    const int n = n0 + tx * 8;
    if (n < N) {
#pragma unroll
        for (int i = 0; i < 4; i++) {
            int m = ty * 4 + i;
            *(ulonglong2*)&P[(size_t)m * ldp + n]     = make_ulonglong2(acc[i][0], acc[i][1]);
            *(ulonglong2*)&P[(size_t)m * ldp + n + 4] = make_ulonglong2(acc[i][2], acc[i][3]);
    }
    }
}

// ---------------- fused x-side GEMMs ----------------
__global__ __launch_bounds__(128) void mega_xgemm(const float* __restrict__ x,
                                                  const float* __restrict__ centroids,
                                                  const float* __restrict__ W_hall,
                                                  const float* __restrict__ W_sel) {
    const int t  = blockIdx.x;
    const int ks = blockIdx.y;
    const float* Bm; float* P; int N, n0, ldp;
    if (t < 16)      { Bm = centroids; P = g_p_dot[ks];  N = C_; n0 = t * 64;        ldp = CP; }
    else if (t < 32) { Bm = W_hall;    P = g_p_hall[ks]; N = C_; n0 = (t - 16) * 64; ldp = CP; }
    else             { Bm = W_sel;     P = g_p_sel[ks];  N = F_; n0 = (t - 32) * 64; ldp = F_; }
    gemm64_nt(x, F_, Bm, F_, P, ldp, N, n0, ks * (F_ / KS), F_ / KS);
}

// ---------------- cos GEMM ----------------
__global__ __launch_bounds__(128) void cos_gemm(const float* __restrict__ W_cos) {
    gemm64_nt(g_feat, F_, W_cos, F_, g_p_cos[blockIdx.y], CP, C_,
              blockIdx.x * 64, blockIdx.y * (F_ / KSC), F_ / KSC);
}

// ---------------- mem GEMM (NN): vm @ centroids; vm tail zero-padded ----------------
__global__ __launch_bounds__(128) void mem_gemm(const float* __restrict__ centroids) {
    __shared__ float As[2][16][68];
    __shared__ float Bs[2][16][68];
    const int n0  = blockIdx.x * 64;
    const int k0  = blockIdx.y * 64;          // KS=16 chunks of 64, covers padded 1024
    const int tid = threadIdx.x;
    const int tx  = tid & 7, ty = tid >> 3;
    const int lr  = tid >> 2, lkq = (tid & 3) * 4;
    const int bk  = tid >> 3;                 // B loader k-row 0..15
    const int bnq = (tid & 7) * 8;

    unsigned long long acc[4][4];
#pragma unroll
    for (int i = 0; i < 4; i++)
#pragma unroll
        for (int j = 0; j < 4; j++) acc[i][j] = 0ull;

    {
        float4 a0 = *(const float4*)&g_vm[lr * CP + k0 + lkq];
        float4 a1 = *(const float4*)&g_vm[(lr + 32) * CP + k0 + lkq];
        int k = k0 + bk;
        float4 b0 = make_float4(0.f,0.f,0.f,0.f), b1 = b0;
        if (k < C_) {
            b0 = *(const float4*)&centroids[(size_t)k * F_ + n0 + bnq];
            b1 = *(const float4*)&centroids[(size_t)k * F_ + n0 + bnq + 4];
        }
        As[0][lkq+0][lr] = a0.x; As[0][lkq+1][lr] = a0.y; As[0][lkq+2][lr] = a0.z; As[0][lkq+3][lr] = a0.w;
        As[0][lkq+0][lr+32] = a1.x; As[0][lkq+1][lr+32] = a1.y; As[0][lkq+2][lr+32] = a1.z; As[0][lkq+3][lr+32] = a1.w;
        *(float4*)&Bs[0][bk][bnq]     = b0;
        *(float4*)&Bs[0][bk][bnq + 4] = b1;
    }
    __syncthreads();

    int buf = 0;
    for (int kb = k0; kb < k0 + 64; kb += 16) {
        const bool hn = (kb + 16) < k0 + 64;
        float4 na0, na1, nb0, nb1;
        if (hn) {
            int kn = kb + 16;
            na0 = *(const float4*)&g_vm[lr * CP + kn + lkq];
            na1 = *(const float4*)&g_vm[(lr + 32) * CP + kn + lkq];
            int k = kn + bk;
            nb0 = make_float4(0.f,0.f,0.f,0.f); nb1 = nb0;
            if (k < C_) {
                nb0 = *(const float4*)&centroids[(size_t)k * F_ + n0 + bnq];
                nb1 = *(const float4*)&centroids[(size_t)k * F_ + n0 + bnq + 4];
            }
        }
        tile_mma(As[buf], Bs[buf], ty, tx, acc);
        if (hn) {
            int nb = buf ^ 1;
            As[nb][lkq+0][lr] = na0.x; As[nb][lkq+1][lr] = na0.y; As[nb][lkq+2][lr] = na0.z; As[nb][lkq+3][lr] = na0.w;
            As[nb][lkq+0][lr+32] = na1.x; As[nb][lkq+1][lr+32] = na1.y; As[nb][lkq+2][lr+32] = na1.z; As[nb][lkq+3][lr+32] = na1.w;
            *(float4*)&Bs[nb][bk][bnq]     = nb0;
            *(float4*)&Bs[nb][bk][bnq + 4] = nb1;
        }
        __syncthreads();
        buf ^= 1;
    }

    float* P = g_p_mem[blockIdx.y];
    const int n = n0 + tx * 8;
#pragma unroll
    for (int i = 0; i < 4; i++) {
        int m = ty * 4 + i;
        *(ulonglong2*)&P[(size_t)m * F_ + n]     = make_ulonglong2(acc[i][0], acc[i][1]);
        *(ulonglong2*)&P[(size_t)m * F_ + n + 4] = make_ulonglong2(acc[i][2], acc[i][3]);
    }
}

// ---------------- per-row: reduce partials, min-dist, softmax, reachability ----------------
__global__ __launch_bounds__(256) void row_softmax_kernel(const float* __restrict__ b_hall) {
    const int b = blockIdx.x;
    const int tid = threadIdx.x;
    __shared__ float r0[256], r1[256];
    float mind2 = 1e30f, maxh = -1e30f;
    const float xn2 = g_xn2[b];
    for (int c = tid; c < C_; c += 256) {
        float dot = 0.f, hv = 0.f;
#pragma unroll
        for (int s = 0; s < KS; s++) {
            dot += g_p_dot[s][b * CP + c];
            hv  += g_p_hall[s][b * CP + c];
        }
        hv += b_hall[c];
        g_hall[b * CP + c] = hv;
        float d2 = xn2 + g_cn2[c] - 2.f * dot;
        mind2 = fminf(mind2, d2);
        maxh  = fmaxf(maxh, hv);
    }
    r0[tid] = mind2; r1[tid] = maxh; __syncthreads();
    for (int o = 128; o > 0; o >>= 1) {
        if (tid < o) { r0[tid] = fminf(r0[tid], r0[tid + o]); r1[tid] = fmaxf(r1[tid], r1[tid + o]); }
        __syncthreads();
    }
    const float md2 = r0[0];
    const float mh  = r1[0];
    __syncthreads();
    float se = 0.f;
    for (int c = tid; c < C_; c += 256) se += __expf(g_hall[b * CP + c] - mh);
    r0[tid] = se; __syncthreads();
    for (int o = 128; o > 0; o >>= 1) {
        if (tid < o) r0[tid] += r0[tid + o];
        __syncthreads();
    }
    const float inv = 1.f / r0[0];
    for (int c = tid; c < C_; c += 256)
        g_vm[b * CP + c] = __expf(g_hall[b * CP + c] - mh) * inv;
    if (tid < CP - C_) g_vm[b * CP + C_ + tid] = 0.f;   // zero pad tail for mem_gemm
    if (tid == 0) g_reach[b] = 10.f / sqrtf(fmaxf(md2, 1e-30f));
}

// ---------------- per-row: feat = reach*(x + tanh(sel)*mem), row norm, outputs ----------------
__global__ __launch_bounds__(256) void combine_kernel(const float* __restrict__ x,
                                                      const float* __restrict__ b_sel,
                                                      float* __restrict__ out, int writeFeat) {
    const int b = blockIdx.x;
    const int tid = threadIdx.x;
    __shared__ float red[256];
    const float reach = g_reach[b];
    float n2 = 0.f;
    for (int f = tid; f < F_; f += 256) {
        float mem = 0.f, sz = 0.f;
#pragma unroll
        for (int s = 0; s < KS; s++) {
            mem += g_p_mem[s][b * F_ + f];
            sz  += g_p_sel[s][b * F_ + f];
        }
        float sel  = tanhf(sz + b_sel[f]);
        float xv   = x[(size_t)b * F_ + f];
        float inf  = sel * mem;
        float feat = reach * (xv + inf);
        g_feat[b * F_ + f] = feat;
        n2 += feat * feat;
        if (writeFeat) {
            out[64000 + b * F_ + f]  = xv;   // direct_feature
            out[195072 + b * F_ + f] = inf;  // infused_feature
        }
    }
    red[tid] = n2; __syncthreads();
    for (int o = 128; o > 0; o >>= 1) {
        if (tid < o) red[tid] += red[tid + o];
        __syncthreads();
    }
    if (tid == 0) g_scale[b] = 16.f / (1.f + sqrtf(red[0]));
}

// ---------------- final logits ----------------
__global__ __launch_bounds__(256) void logits_kernel(float* __restrict__ out) {
    int i = blockIdx.x * 256 + threadIdx.x;
    if (i >= B_ * C_) return;
    int b = i / C_, c = i % C_;
    float s = 0.f;
#pragma unroll
    for (int ss = 0; ss < KSC; ss++) s += g_p_cos[ss][b * CP + c];
    out[i] = s * g_scale[b] / g_wn[c];
}

// ---------------- launch ----------------
extern "C" void kernel_launch(void* const* d_in, const int* in_sizes, int n_in,
                              void* d_out, int out_size) {
    const float* x         = (const float*)d_in[0];
    const float* centroids = (const float*)d_in[1];
    const float* W_hall    = (const float*)d_in[2];
    const float* b_hall    = (const float*)d_in[3];
    const float* W_sel     = (const float*)d_in[4];
    const float* b_sel     = (const float*)d_in[5];
    const float* W_cos     = (const float*)d_in[6];
    float* out = (float*)d_out;

    norms_kernel<<<2 * C_ + B_, 256>>>(centroids, W_cos, x);
    mega_xgemm<<<dim3(64, KS), 128>>>(x, centroids, W_hall, W_sel);
    row_softmax_kernel<<<B_, 256>>>(b_hall);
    mem_gemm<<<dim3(32, KS), 128>>>(centroids);
    int writeFeat = (out_size >= 326144) ? 1 : 0;
    combine_kernel<<<B_, 256>>>(x, b_sel, out, writeFeat);
    cos_gemm<<<dim3(16, KSC), 128>>>(W_cos);
    logits_kernel<<<250, 256>>>(out);
}